// round 13
// baseline (speedup 1.0000x reference)
#include <cuda_runtime.h>
#include <cuda_fp16.h>
#include <stdint.h>

#define N_NODES 100000
#define N_EDGES 1600000
#define NF      128
#define NC      40

// ---------------- static scratch (no allocations allowed) ----------------
static __device__ __half g_h [(size_t)N_NODES * NF];        // 25.6 MB
static __device__ __half g_hd[(size_t)N_NODES * NF];        // 25.6 MB
static __device__ __half g_t2[(size_t)N_NODES * NC + 64];   // 8 MB (+pad)
static __device__ __half g_wt[128 * 128];                   // W1^T fp16
static __device__ float  g_dinv[N_NODES];
static __device__ int    g_cnt[N_NODES];
static __device__ int    g_rowptr[N_NODES + 1];
static __device__ int    g_cursor[N_NODES];
static __device__ int    g_csr_src[N_EDGES];                // 6.4 MB
static __device__ int    g_blocksum[128];
static __device__ int    g_ctr1;                            // agg1 work cursor
static __device__ int    g_ctr2;                            // agg2 work cursor

// ---------------- packed f32x2 helpers (Blackwell dual-rate fp32) --------
__device__ __forceinline__ uint64_t pack2(float lo, float hi) {
    uint64_t r;
    asm("mov.b64 %0, {%1, %2};" : "=l"(r) : "f"(lo), "f"(hi));
    return r;
}
__device__ __forceinline__ void fma2(uint64_t& d, uint64_t a, uint64_t b) {
    asm("fma.rn.f32x2 %0, %1, %2, %0;" : "+l"(d) : "l"(a), "l"(b));
}
__device__ __forceinline__ float2 unpack2(uint64_t v) {
    float2 f;
    asm("mov.b64 {%0, %1}, %2;" : "=f"(f.x), "=f"(f.y) : "l"(v));
    return f;
}

// ---------------- threefry2x32, key = (0, 42) ----------------
__device__ __forceinline__ uint32_t rotl32(uint32_t x, int r) {
    return (x << r) | (x >> (32 - r));
}

__device__ __forceinline__ void threefry_0_42(uint32_t& x0, uint32_t& x1) {
    const uint32_t K1 = 0u;
    const uint32_t K2 = 42u;
    const uint32_t KC = 0x1BD11BDAu ^ K1 ^ K2;
#define TF_ROUND(r) { x0 += x1; x1 = rotl32(x1, r); x1 ^= x0; }
    x0 += K1; x1 += K2;
    TF_ROUND(13) TF_ROUND(15) TF_ROUND(26) TF_ROUND(6)
    x0 += K2; x1 += KC + 1u;
    TF_ROUND(17) TF_ROUND(29) TF_ROUND(16) TF_ROUND(24)
    x0 += KC; x1 += K1 + 2u;
    TF_ROUND(13) TF_ROUND(15) TF_ROUND(26) TF_ROUND(6)
    x0 += K1; x1 += K2 + 3u;
    TF_ROUND(17) TF_ROUND(29) TF_ROUND(16) TF_ROUND(24)
    x0 += K2; x1 += KC + 4u;
    TF_ROUND(13) TF_ROUND(15) TF_ROUND(26) TF_ROUND(6)
    x0 += KC; x1 += K1 + 5u;
#undef TF_ROUND
}

__device__ __forceinline__ float drop_scale(uint32_t i) {
    uint32_t a = 0u, b = i;
    threefry_0_42(a, b);
    return ((a ^ b) >> 31) ? 2.0f : 0.0f;
}

// -------- prep: g_wt[n][k] = (half)W1[k][n]; also reset work cursors -----
__global__ void k_prep_wt(const float* __restrict__ W) {
    int idx = blockIdx.x * 256 + threadIdx.x;   // 64 blocks x 256
    if (idx == 0) { g_ctr1 = 0; g_ctr2 = 0; }
    int k = idx >> 7;
    int n = idx & 127;
    g_wt[n * 128 + k] = __float2half(W[(size_t)k * 128 + n]);
}

// ---------------- small kernels: degree / CSR build ----------------
__global__ void k_zero(int N) {
    int i = blockIdx.x * blockDim.x + threadIdx.x;
    if (i < N) g_cnt[i] = 0;
}

__global__ void k_count(const int* __restrict__ ei, int E) {
    int e = blockIdx.x * blockDim.x + threadIdx.x;
    if (e < E) atomicAdd(&g_cnt[ei[E + e]], 1);
}

__global__ void k_scan1(int N) {  // per-1024-block sums
    __shared__ int s[1024];
    int t = threadIdx.x;
    int i = blockIdx.x * 1024 + t;
    s[t] = (i < N) ? g_cnt[i] : 0;
    __syncthreads();
    for (int off = 512; off > 0; off >>= 1) {
        if (t < off) s[t] += s[t + off];
        __syncthreads();
    }
    if (t == 0) g_blocksum[blockIdx.x] = s[0];
}

// scan3 folds the cross-block exclusive scan: each block parallel-reduces
// g_blocksum[0..blockIdx.x) for its base.
__global__ void k_scan3(int nb, int N) {
    __shared__ int s[1024];
    __shared__ int aux[128];
    int t = threadIdx.x;
    int i = blockIdx.x * 1024 + t;
    if (t < 128) aux[t] = (t < blockIdx.x && t < nb) ? g_blocksum[t] : 0;
    int v = (i < N) ? g_cnt[i] : 0;
    s[t] = v;
    __syncthreads();
    if (t < 64) aux[t] += aux[t + 64];
    __syncthreads();
    if (t < 32) aux[t] += aux[t + 32];
    __syncthreads();
    if (t < 16) aux[t] += aux[t + 16];
    __syncthreads();
    if (t < 8)  aux[t] += aux[t + 8];
    __syncthreads();
    if (t < 4)  aux[t] += aux[t + 4];
    __syncthreads();
    if (t < 2)  aux[t] += aux[t + 2];
    __syncthreads();
    if (t < 1)  aux[t] += aux[t + 1];
    __syncthreads();
    int base = aux[0];
    for (int off = 1; off < 1024; off <<= 1) {
        int x = (t >= off) ? s[t - off] : 0;
        __syncthreads();
        s[t] += x;
        __syncthreads();
    }
    if (i < N) {
        int excl = s[t] - v + base;
        g_rowptr[i] = excl;
        g_cursor[i] = excl;
        g_dinv[i]   = rsqrtf((float)(v + 1));
        if (i == N - 1) g_rowptr[N] = excl + v;
    }
}

__global__ void k_fill(const int* __restrict__ ei, int E) {
    int e = blockIdx.x * blockDim.x + threadIdx.x;
    if (e < E) {
        int d   = ei[E + e];
        int pos = atomicAdd(&g_cursor[d], 1);
        g_csr_src[pos] = ei[e];
    }
}

// ---------------- GEMM1: h = x @ W1, fp16 tensor cores (mma.sync) --------
// R10 configuration: direct __ldcs A loads, launch_bounds(256,3).
__device__ __forceinline__ void mma16816(float c[4],
                                         uint32_t a0, uint32_t a1,
                                         uint32_t a2, uint32_t a3,
                                         uint32_t b0, uint32_t b1) {
    asm volatile(
        "mma.sync.aligned.m16n8k16.row.col.f32.f16.f16.f32 "
        "{%0,%1,%2,%3}, {%4,%5,%6,%7}, {%8,%9}, {%0,%1,%2,%3};"
        : "+f"(c[0]), "+f"(c[1]), "+f"(c[2]), "+f"(c[3])
        : "r"(a0), "r"(a1), "r"(a2), "r"(a3), "r"(b0), "r"(b1));
}

__device__ __forceinline__ uint32_t f2h2(float2 v) {
    __half2 h = __floats2half2_rn(v.x, v.y);
    return *(uint32_t*)&h;
}

__global__ __launch_bounds__(256, 3) void k_gemm1(const float* __restrict__ x,
                                                  int M) {
    __shared__ __align__(16) __half Wt[128 * 128];  // 32 KB, rotated rows

    int tid  = threadIdx.x;
    int row0 = blockIdx.x * 64;

    // stage rotated copy of g_wt: uint4 seg s of row n -> seg (s + (n&15))&15
    for (int i = tid; i < 128 * 16; i += 256) {
        int n = i >> 4;
        int s = i & 15;
        ((uint4*)(Wt + n * 128))[(s + (n & 15)) & 15] =
            ((const uint4*)(g_wt + n * 128))[s];
    }
    __syncthreads();

    int warp = tid >> 5;
    int lane = tid & 31;
    int g = lane >> 2;       // 0..7
    int t = lane & 3;        // 0..3
    int rg = warp >> 1;      // 0..3 row group
    int ch = warp & 1;       // 0..1 col half

    int r_lo = row0 + rg * 16 + g;
    int r_hi = r_lo + 8;
    bool lo_ok = r_lo < M;
    bool hi_ok = r_hi < M;
    const float* xlo = x + (size_t)r_lo * 128 + 2 * t;
    const float* xhi = x + (size_t)r_hi * 128 + 2 * t;

    float acc[8][4];
#pragma unroll
    for (int nt = 0; nt < 8; nt++)
#pragma unroll
        for (int j = 0; j < 4; j++) acc[nt][j] = 0.f;

#pragma unroll
    for (int k0 = 0; k0 < 128; k0 += 16) {
        uint32_t a0 = 0u, a1 = 0u, a2 = 0u, a3 = 0u;
        if (lo_ok) {
            a0 = f2h2(__ldcs((const float2*)(xlo + k0)));
            a2 = f2h2(__ldcs((const float2*)(xlo + k0 + 8)));
        }
        if (hi_ok) {
            a1 = f2h2(__ldcs((const float2*)(xhi + k0)));
            a3 = f2h2(__ldcs((const float2*)(xhi + k0 + 8)));
        }
#pragma unroll
        for (int nt = 0; nt < 8; nt++) {
            int n  = ch * 64 + nt * 8 + g;
            int rot = 8 * (n & 15);
            int h0 = (k0 + 2 * t + rot) & 127;
            int h1 = (k0 + 2 * t + 8 + rot) & 127;
            uint32_t b0 = *(uint32_t*)&Wt[n * 128 + h0];
            uint32_t b1 = *(uint32_t*)&Wt[n * 128 + h1];
            mma16816(acc[nt], a0, a1, a2, a3, b0, b1);
        }
    }

    // epilogue: store fp16 h
#pragma unroll
    for (int nt = 0; nt < 8; nt++) {
        int col = ch * 64 + nt * 8 + 2 * t;
        if (lo_ok) {
            __half2 hv = __floats2half2_rn(acc[nt][0], acc[nt][1]);
            *(uint32_t*)(g_h + (size_t)r_lo * 128 + col) = *(uint32_t*)&hv;
        }
        if (hi_ok) {
            __half2 hv = __floats2half2_rn(acc[nt][2], acc[nt][3]);
            *(uint32_t*)(g_h + (size_t)r_hi * 128 + col) = *(uint32_t*)&hv;
        }
    }
}

// ---- agg1: hd = dropout(relu(A_norm @ h + b1)), stored fp16 ----
// Persistent warps: each warp grabs 4-node batches from g_ctr1 until done.
__device__ __forceinline__ void acc_half4(float4& acc, uint2 raw, float w) {
    __half2 lo = *(__half2*)&raw.x;
    __half2 hi = *(__half2*)&raw.y;
    float2 f0 = __half22float2(lo);
    float2 f1 = __half22float2(hi);
    acc.x = fmaf(f0.x, w, acc.x);
    acc.y = fmaf(f0.y, w, acc.y);
    acc.z = fmaf(f1.x, w, acc.z);
    acc.w = fmaf(f1.y, w, acc.w);
}

__global__ void k_agg1(const float* __restrict__ b1, int N) {
    int lane = threadIdx.x & 31;

    for (;;) {
        int base;
        if (lane == 0) base = atomicAdd(&g_ctr1, 4);
        base = __shfl_sync(0xffffffffu, base, 0);
        if (base >= N) return;
        int nend = (base + 4 < N) ? base + 4 : N;

        for (int n = base; n < nend; n++) {
            float di = g_dinv[n];
            float wself = di * di;

            float4 acc = make_float4(0.f, 0.f, 0.f, 0.f);
            {
                uint2 raw = ((const uint2*)(g_h + (size_t)n * 128))[lane];
                acc_half4(acc, raw, wself);
            }

            int e  = g_rowptr[n];
            int e1 = g_rowptr[n + 1];

            for (; e + 8 <= e1; e += 8) {
                int   si[8];
                float wi[8];
                uint2 vi[8];
#pragma unroll
                for (int u = 0; u < 8; u++) si[u] = g_csr_src[e + u];
#pragma unroll
                for (int u = 0; u < 8; u++) wi[u] = g_dinv[si[u]] * di;
#pragma unroll
                for (int u = 0; u < 8; u++)
                    vi[u] = ((const uint2*)(g_h + (size_t)si[u] * 128))[lane];
#pragma unroll
                for (int u = 0; u < 8; u++) acc_half4(acc, vi[u], wi[u]);
            }
            for (; e < e1; e++) {
                int s   = g_csr_src[e];
                float w = g_dinv[s] * di;
                uint2 raw = ((const uint2*)(g_h + (size_t)s * 128))[lane];
                acc_half4(acc, raw, w);
            }

            uint32_t mi = (uint32_t)n * 128u + (uint32_t)lane * 4u;
            float4 bb = ((const float4*)b1)[lane];
            float f0 = fmaxf(acc.x + bb.x, 0.f) * drop_scale(mi + 0u);
            float f1 = fmaxf(acc.y + bb.y, 0.f) * drop_scale(mi + 1u);
            float f2 = fmaxf(acc.z + bb.z, 0.f) * drop_scale(mi + 2u);
            float f3 = fmaxf(acc.w + bb.w, 0.f) * drop_scale(mi + 3u);

            __half2 h0 = __floats2half2_rn(f0, f1);
            __half2 h1 = __floats2half2_rn(f2, f3);
            uint2 pkt;
            pkt.x = *(uint32_t*)&h0;
            pkt.y = *(uint32_t*)&h1;
            ((uint2*)(g_hd + (size_t)n * 128))[lane] = pkt;
        }
    }
}

// ---------------- GEMM2: t2 = hd @ W2  (fp16 in, fp32 acc, fp16 out) -----
#define G2_ROWS 64
__global__ __launch_bounds__(320) void k_gemm2(const float* __restrict__ W2,
                                               int M) {
    __shared__ __align__(16) __half Xs[128 * G2_ROWS];   // 16 KB
    __shared__ __align__(16) float  Ws[128 * NC];        // 20 KB

    int tid  = threadIdx.x;
    int row0 = blockIdx.x * G2_ROWS;

    for (int i = tid; i < 128 * NC / 4; i += 320)
        ((float4*)Ws)[i] = ((const float4*)W2)[i];

    for (int i = tid; i < G2_ROWS * 16; i += 320) {
        int m  = i / 16;
        int k8 = (i % 16) * 8;
        uint4 v = make_uint4(0u, 0u, 0u, 0u);
        if (row0 + m < M)
            v = ((const uint4*)(g_hd + (size_t)(row0 + m) * 128))[i % 16];
        __half* hp = (__half*)&v;
#pragma unroll
        for (int j = 0; j < 8; j++) Xs[(k8 + j) * G2_ROWS + m] = hp[j];
    }
    __syncthreads();

    int w    = tid >> 5;
    int lane = tid & 31;
    int c0   = w * 4;

    uint64_t a00 = pack2(0.f, 0.f), a01 = a00;
    uint64_t a10 = a00, a11 = a00;

#pragma unroll 4
    for (int k = 0; k < 128; k++) {
        __half2 xv = *(__half2*)&Xs[k * G2_ROWS + 2 * lane];
        float2  xf = __half22float2(xv);
        float4  wv = *(const float4*)&Ws[k * NC + c0];
        uint64_t w01 = pack2(wv.x, wv.y);
        uint64_t w23 = pack2(wv.z, wv.w);
        uint64_t x0  = pack2(xf.x, xf.x);
        uint64_t x1  = pack2(xf.y, xf.y);
        fma2(a00, x0, w01); fma2(a01, x0, w23);
        fma2(a10, x1, w01); fma2(a11, x1, w23);
    }

    int m0 = row0 + 2 * lane;
    if (m0 < M) {
        float2 p0 = unpack2(a00), p1 = unpack2(a01);
        __half2 h0 = __float22half2_rn(p0);
        __half2 h1 = __float22half2_rn(p1);
        uint2 pkt; pkt.x = *(uint32_t*)&h0; pkt.y = *(uint32_t*)&h1;
        *(uint2*)(g_t2 + (size_t)m0 * NC + c0) = pkt;
    }
    if (m0 + 1 < M) {
        float2 p0 = unpack2(a10), p1 = unpack2(a11);
        __half2 h0 = __float22half2_rn(p0);
        __half2 h1 = __float22half2_rn(p1);
        uint2 pkt; pkt.x = *(uint32_t*)&h0; pkt.y = *(uint32_t*)&h1;
        *(uint2*)(g_t2 + (size_t)(m0 + 1) * NC + c0) = pkt;
    }
}

// ---------------- agg2: out = A_norm @ t2 + b2  (persistent warps) -------
__global__ void k_agg2(const float* __restrict__ b2,
                       float* __restrict__ out,
                       int N) {
    int lane = threadIdx.x & 31;
    bool active = lane < 20;

    for (;;) {
        int base;
        if (lane == 0) base = atomicAdd(&g_ctr2, 4);
        base = __shfl_sync(0xffffffffu, base, 0);
        if (base >= N) return;
        int nend = (base + 4 < N) ? base + 4 : N;

        for (int n = base; n < nend; n++) {
            float di = g_dinv[n];
            float wself = di * di;

            float2 a = make_float2(0.f, 0.f);
            if (active) {
                __half2 v = ((const __half2*)(g_t2 + (size_t)n * NC))[lane];
                float2 f = __half22float2(v);
                a.x = f.x * wself;
                a.y = f.y * wself;
            }

            int e  = g_rowptr[n];
            int e1 = g_rowptr[n + 1];

            for (; e + 8 <= e1; e += 8) {
                int     si[8];
                float   wi[8];
                __half2 vi[8];
#pragma unroll
                for (int u = 0; u < 8; u++) si[u] = g_csr_src[e + u];
#pragma unroll
                for (int u = 0; u < 8; u++) wi[u] = g_dinv[si[u]] * di;
#pragma unroll
                for (int u = 0; u < 8; u++)
                    vi[u] = active
                          ? ((const __half2*)(g_t2 + (size_t)si[u] * NC))[lane]
                          : __half2();
#pragma unroll
                for (int u = 0; u < 8; u++) {
                    float2 f = __half22float2(vi[u]);
                    a.x = fmaf(f.x, wi[u], a.x);
                    a.y = fmaf(f.y, wi[u], a.y);
                }
            }
            for (; e < e1; e++) {
                int s   = g_csr_src[e];
                float w = g_dinv[s] * di;
                if (active) {
                    __half2 v = ((const __half2*)(g_t2 + (size_t)s * NC))[lane];
                    float2 f = __half22float2(v);
                    a.x = fmaf(f.x, w, a.x);
                    a.y = fmaf(f.y, w, a.y);
                }
            }

            if (active) {
                float2 bv = ((const float2*)b2)[lane];
                float2 o = make_float2(a.x + bv.x, a.y + bv.y);
                *(float2*)(out + (size_t)n * NC + 2 * lane) = o;
            }
        }
    }
}

// ---------------- launch ----------------
// k_gemm1 stays 4th: ncu's capture hits that slot.
extern "C" void kernel_launch(void* const* d_in, const int* in_sizes, int n_in,
                              void* d_out, int out_size) {
    const float* x  = (const float*)d_in[0];
    const int*   ei = (const int*)d_in[1];
    const float* W1 = (const float*)d_in[2];
    const float* b1 = (const float*)d_in[3];
    const float* W2 = (const float*)d_in[4];
    const float* b2 = (const float*)d_in[5];
    float* out = (float*)d_out;

    const int N = N_NODES;
    const int E = N_EDGES;
    const int nb = (N + 1023) / 1024;   // 98

    k_prep_wt <<<64, 256>>>(W1);
    k_zero  <<<(N + 255) / 256, 256>>>(N);
    k_count <<<(E + 255) / 256, 256>>>(ei, E);
    k_gemm1 <<<(N + 63) / 64, 256>>>(x, N);   // slot 4 for ncu
    k_scan1 <<<nb, 1024>>>(N);
    k_scan3 <<<nb, 1024>>>(nb, N);
    k_fill  <<<(E + 255) / 256, 256>>>(ei, E);
    k_agg1  <<<148 * 8, 256>>>(b1, N);        // persistent work-stealing
    k_gemm2 <<<(N + G2_ROWS - 1) / G2_ROWS, 320>>>(W2, N);
    k_agg2  <<<148 * 8, 256>>>(b2, out, N);   // persistent work-stealing
}

// round 14
// speedup vs baseline: 1.0947x; 1.0947x over previous
#include <cuda_runtime.h>
#include <cuda_fp16.h>
#include <stdint.h>

#define N_NODES 100000
#define N_EDGES 1600000
#define NF      128
#define NC      40

// ---------------- static scratch (no allocations allowed) ----------------
static __device__ __half g_h [(size_t)N_NODES * NF];        // 25.6 MB
static __device__ __half g_hd[(size_t)N_NODES * NF];        // 25.6 MB
static __device__ __half g_t2[(size_t)N_NODES * NC + 64];   // 8 MB (+pad)
static __device__ __half g_wt[128 * 128];                   // W1^T fp16
static __device__ float  g_dinv[N_NODES];
static __device__ int    g_cnt[N_NODES];
static __device__ int    g_rowptr[N_NODES + 1];
static __device__ int    g_cursor[N_NODES];
static __device__ int    g_csr_src[N_EDGES];                // 6.4 MB
static __device__ float  g_csr_w[N_EDGES];                  // 6.4 MB: dinv[src]
static __device__ int    g_blocksum[128];

// ---------------- packed f32x2 helpers (Blackwell dual-rate fp32) --------
__device__ __forceinline__ uint64_t pack2(float lo, float hi) {
    uint64_t r;
    asm("mov.b64 %0, {%1, %2};" : "=l"(r) : "f"(lo), "f"(hi));
    return r;
}
__device__ __forceinline__ void fma2(uint64_t& d, uint64_t a, uint64_t b) {
    asm("fma.rn.f32x2 %0, %1, %2, %0;" : "+l"(d) : "l"(a), "l"(b));
}
__device__ __forceinline__ float2 unpack2(uint64_t v) {
    float2 f;
    asm("mov.b64 {%0, %1}, %2;" : "=f"(f.x), "=f"(f.y) : "l"(v));
    return f;
}

// ---------------- threefry2x32, key = (0, 42) ----------------
__device__ __forceinline__ uint32_t rotl32(uint32_t x, int r) {
    return (x << r) | (x >> (32 - r));
}

__device__ __forceinline__ void threefry_0_42(uint32_t& x0, uint32_t& x1) {
    const uint32_t K1 = 0u;
    const uint32_t K2 = 42u;
    const uint32_t KC = 0x1BD11BDAu ^ K1 ^ K2;
#define TF_ROUND(r) { x0 += x1; x1 = rotl32(x1, r); x1 ^= x0; }
    x0 += K1; x1 += K2;
    TF_ROUND(13) TF_ROUND(15) TF_ROUND(26) TF_ROUND(6)
    x0 += K2; x1 += KC + 1u;
    TF_ROUND(17) TF_ROUND(29) TF_ROUND(16) TF_ROUND(24)
    x0 += KC; x1 += K1 + 2u;
    TF_ROUND(13) TF_ROUND(15) TF_ROUND(26) TF_ROUND(6)
    x0 += K1; x1 += K2 + 3u;
    TF_ROUND(17) TF_ROUND(29) TF_ROUND(16) TF_ROUND(24)
    x0 += K2; x1 += KC + 4u;
    TF_ROUND(13) TF_ROUND(15) TF_ROUND(26) TF_ROUND(6)
    x0 += KC; x1 += K1 + 5u;
#undef TF_ROUND
}

__device__ __forceinline__ float drop_scale(uint32_t i) {
    uint32_t a = 0u, b = i;
    threefry_0_42(a, b);
    return ((a ^ b) >> 31) ? 2.0f : 0.0f;
}

// -------- prep: g_wt[n][k] = (half)W1[k][n] --------
__global__ void k_prep_wt(const float* __restrict__ W) {
    int idx = blockIdx.x * 256 + threadIdx.x;   // 64 blocks x 256
    int k = idx >> 7;
    int n = idx & 127;
    g_wt[n * 128 + k] = __float2half(W[(size_t)k * 128 + n]);
}

// ---------------- small kernels: degree / CSR build ----------------
__global__ void k_zero(int N) {
    int i = blockIdx.x * blockDim.x + threadIdx.x;
    if (i < N) g_cnt[i] = 0;
}

__global__ void k_count(const int* __restrict__ ei, int E) {
    int e = blockIdx.x * blockDim.x + threadIdx.x;
    if (e < E) atomicAdd(&g_cnt[ei[E + e]], 1);
}

__global__ void k_scan1(int N) {  // per-1024-block sums
    __shared__ int s[1024];
    int t = threadIdx.x;
    int i = blockIdx.x * 1024 + t;
    s[t] = (i < N) ? g_cnt[i] : 0;
    __syncthreads();
    for (int off = 512; off > 0; off >>= 1) {
        if (t < off) s[t] += s[t + off];
        __syncthreads();
    }
    if (t == 0) g_blocksum[blockIdx.x] = s[0];
}

// scan3 folds the cross-block exclusive scan: each block parallel-reduces
// g_blocksum[0..blockIdx.x) for its base.
__global__ void k_scan3(int nb, int N) {
    __shared__ int s[1024];
    __shared__ int aux[128];
    int t = threadIdx.x;
    int i = blockIdx.x * 1024 + t;
    if (t < 128) aux[t] = (t < blockIdx.x && t < nb) ? g_blocksum[t] : 0;
    int v = (i < N) ? g_cnt[i] : 0;
    s[t] = v;
    __syncthreads();
    if (t < 64) aux[t] += aux[t + 64];
    __syncthreads();
    if (t < 32) aux[t] += aux[t + 32];
    __syncthreads();
    if (t < 16) aux[t] += aux[t + 16];
    __syncthreads();
    if (t < 8)  aux[t] += aux[t + 8];
    __syncthreads();
    if (t < 4)  aux[t] += aux[t + 4];
    __syncthreads();
    if (t < 2)  aux[t] += aux[t + 2];
    __syncthreads();
    if (t < 1)  aux[t] += aux[t + 1];
    __syncthreads();
    int base = aux[0];
    for (int off = 1; off < 1024; off <<= 1) {
        int x = (t >= off) ? s[t - off] : 0;
        __syncthreads();
        s[t] += x;
        __syncthreads();
    }
    if (i < N) {
        int excl = s[t] - v + base;
        g_rowptr[i] = excl;
        g_cursor[i] = excl;
        g_dinv[i]   = rsqrtf((float)(v + 1));
        if (i == N - 1) g_rowptr[N] = excl + v;
    }
}

// fill also precomputes per-edge source weight dinv[src] so the agg loops
// lose one gather level (idx -> dinv chain removed).
__global__ void k_fill(const int* __restrict__ ei, int E) {
    int e = blockIdx.x * blockDim.x + threadIdx.x;
    if (e < E) {
        int d   = ei[E + e];
        int s   = ei[e];
        int pos = atomicAdd(&g_cursor[d], 1);
        g_csr_src[pos] = s;
        g_csr_w[pos]   = g_dinv[s];
    }
}

// ---------------- GEMM1: h = x @ W1, fp16 tensor cores (mma.sync) --------
// Direct __ldcs A loads, launch_bounds(256,3), rotated Wt rows.
__device__ __forceinline__ void mma16816(float c[4],
                                         uint32_t a0, uint32_t a1,
                                         uint32_t a2, uint32_t a3,
                                         uint32_t b0, uint32_t b1) {
    asm volatile(
        "mma.sync.aligned.m16n8k16.row.col.f32.f16.f16.f32 "
        "{%0,%1,%2,%3}, {%4,%5,%6,%7}, {%8,%9}, {%0,%1,%2,%3};"
        : "+f"(c[0]), "+f"(c[1]), "+f"(c[2]), "+f"(c[3])
        : "r"(a0), "r"(a1), "r"(a2), "r"(a3), "r"(b0), "r"(b1));
}

__device__ __forceinline__ uint32_t f2h2(float2 v) {
    __half2 h = __floats2half2_rn(v.x, v.y);
    return *(uint32_t*)&h;
}

__global__ __launch_bounds__(256, 3) void k_gemm1(const float* __restrict__ x,
                                                  int M) {
    __shared__ __align__(16) __half Wt[128 * 128];  // 32 KB, rotated rows

    int tid  = threadIdx.x;
    int row0 = blockIdx.x * 64;

    for (int i = tid; i < 128 * 16; i += 256) {
        int n = i >> 4;
        int s = i & 15;
        ((uint4*)(Wt + n * 128))[(s + (n & 15)) & 15] =
            ((const uint4*)(g_wt + n * 128))[s];
    }
    __syncthreads();

    int warp = tid >> 5;
    int lane = tid & 31;
    int g = lane >> 2;
    int t = lane & 3;
    int rg = warp >> 1;
    int ch = warp & 1;

    int r_lo = row0 + rg * 16 + g;
    int r_hi = r_lo + 8;
    bool lo_ok = r_lo < M;
    bool hi_ok = r_hi < M;
    const float* xlo = x + (size_t)r_lo * 128 + 2 * t;
    const float* xhi = x + (size_t)r_hi * 128 + 2 * t;

    float acc[8][4];
#pragma unroll
    for (int nt = 0; nt < 8; nt++)
#pragma unroll
        for (int j = 0; j < 4; j++) acc[nt][j] = 0.f;

#pragma unroll
    for (int k0 = 0; k0 < 128; k0 += 16) {
        uint32_t a0 = 0u, a1 = 0u, a2 = 0u, a3 = 0u;
        if (lo_ok) {
            a0 = f2h2(__ldcs((const float2*)(xlo + k0)));
            a2 = f2h2(__ldcs((const float2*)(xlo + k0 + 8)));
        }
        if (hi_ok) {
            a1 = f2h2(__ldcs((const float2*)(xhi + k0)));
            a3 = f2h2(__ldcs((const float2*)(xhi + k0 + 8)));
        }
#pragma unroll
        for (int nt = 0; nt < 8; nt++) {
            int n  = ch * 64 + nt * 8 + g;
            int rot = 8 * (n & 15);
            int h0 = (k0 + 2 * t + rot) & 127;
            int h1 = (k0 + 2 * t + 8 + rot) & 127;
            uint32_t b0 = *(uint32_t*)&Wt[n * 128 + h0];
            uint32_t b1 = *(uint32_t*)&Wt[n * 128 + h1];
            mma16816(acc[nt], a0, a1, a2, a3, b0, b1);
        }
    }

#pragma unroll
    for (int nt = 0; nt < 8; nt++) {
        int col = ch * 64 + nt * 8 + 2 * t;
        if (lo_ok) {
            __half2 hv = __floats2half2_rn(acc[nt][0], acc[nt][1]);
            *(uint32_t*)(g_h + (size_t)r_lo * 128 + col) = *(uint32_t*)&hv;
        }
        if (hi_ok) {
            __half2 hv = __floats2half2_rn(acc[nt][2], acc[nt][3]);
            *(uint32_t*)(g_h + (size_t)r_hi * 128 + col) = *(uint32_t*)&hv;
        }
    }
}

// ---- agg1: hd = dropout(relu(A_norm @ h + b1)), stored fp16 ----
__device__ __forceinline__ void acc_half4(float4& acc, uint2 raw, float w) {
    __half2 lo = *(__half2*)&raw.x;
    __half2 hi = *(__half2*)&raw.y;
    float2 f0 = __half22float2(lo);
    float2 f1 = __half22float2(hi);
    acc.x = fmaf(f0.x, w, acc.x);
    acc.y = fmaf(f0.y, w, acc.y);
    acc.z = fmaf(f1.x, w, acc.z);
    acc.w = fmaf(f1.y, w, acc.w);
}

__global__ void k_agg1(const float* __restrict__ b1, int N) {
    int warp = threadIdx.x >> 5;
    int lane = threadIdx.x & 31;
    int n = blockIdx.x * (blockDim.x >> 5) + warp;
    if (n >= N) return;

    float di = g_dinv[n];
    float wself = di * di;

    float4 acc = make_float4(0.f, 0.f, 0.f, 0.f);
    {
        uint2 raw = ((const uint2*)(g_h + (size_t)n * 128))[lane];
        acc_half4(acc, raw, wself);
    }

    int e  = g_rowptr[n];
    int e1 = g_rowptr[n + 1];

    for (; e + 8 <= e1; e += 8) {
        int   si[8];
        float wi[8];
        uint2 vi[8];
#pragma unroll
        for (int u = 0; u < 8; u++) si[u] = g_csr_src[e + u];
#pragma unroll
        for (int u = 0; u < 8; u++) wi[u] = g_csr_w[e + u] * di;
#pragma unroll
        for (int u = 0; u < 8; u++)
            vi[u] = ((const uint2*)(g_h + (size_t)si[u] * 128))[lane];
#pragma unroll
        for (int u = 0; u < 8; u++) acc_half4(acc, vi[u], wi[u]);
    }
    for (; e < e1; e++) {
        int s   = g_csr_src[e];
        float w = g_csr_w[e] * di;
        uint2 raw = ((const uint2*)(g_h + (size_t)s * 128))[lane];
        acc_half4(acc, raw, w);
    }

    uint32_t mi = (uint32_t)n * 128u + (uint32_t)lane * 4u;
    float4 bb = ((const float4*)b1)[lane];
    float f0 = fmaxf(acc.x + bb.x, 0.f) * drop_scale(mi + 0u);
    float f1 = fmaxf(acc.y + bb.y, 0.f) * drop_scale(mi + 1u);
    float f2 = fmaxf(acc.z + bb.z, 0.f) * drop_scale(mi + 2u);
    float f3 = fmaxf(acc.w + bb.w, 0.f) * drop_scale(mi + 3u);

    __half2 h0 = __floats2half2_rn(f0, f1);
    __half2 h1 = __floats2half2_rn(f2, f3);
    uint2 pkt;
    pkt.x = *(uint32_t*)&h0;
    pkt.y = *(uint32_t*)&h1;
    ((uint2*)(g_hd + (size_t)n * 128))[lane] = pkt;
}

// ---------------- GEMM2: t2 = hd @ W2  (fp16 in, fp32 acc, fp16 out) -----
#define G2_ROWS 64
__global__ __launch_bounds__(320) void k_gemm2(const float* __restrict__ W2,
                                               int M) {
    __shared__ __align__(16) __half Xs[128 * G2_ROWS];   // 16 KB
    __shared__ __align__(16) float  Ws[128 * NC];        // 20 KB

    int tid  = threadIdx.x;
    int row0 = blockIdx.x * G2_ROWS;

    for (int i = tid; i < 128 * NC / 4; i += 320)
        ((float4*)Ws)[i] = ((const float4*)W2)[i];

    for (int i = tid; i < G2_ROWS * 16; i += 320) {
        int m  = i / 16;
        int k8 = (i % 16) * 8;
        uint4 v = make_uint4(0u, 0u, 0u, 0u);
        if (row0 + m < M)
            v = ((const uint4*)(g_hd + (size_t)(row0 + m) * 128))[i % 16];
        __half* hp = (__half*)&v;
#pragma unroll
        for (int j = 0; j < 8; j++) Xs[(k8 + j) * G2_ROWS + m] = hp[j];
    }
    __syncthreads();

    int w    = tid >> 5;
    int lane = tid & 31;
    int c0   = w * 4;

    uint64_t a00 = pack2(0.f, 0.f), a01 = a00;
    uint64_t a10 = a00, a11 = a00;

#pragma unroll 4
    for (int k = 0; k < 128; k++) {
        __half2 xv = *(__half2*)&Xs[k * G2_ROWS + 2 * lane];
        float2  xf = __half22float2(xv);
        float4  wv = *(const float4*)&Ws[k * NC + c0];
        uint64_t w01 = pack2(wv.x, wv.y);
        uint64_t w23 = pack2(wv.z, wv.w);
        uint64_t x0  = pack2(xf.x, xf.x);
        uint64_t x1  = pack2(xf.y, xf.y);
        fma2(a00, x0, w01); fma2(a01, x0, w23);
        fma2(a10, x1, w01); fma2(a11, x1, w23);
    }

    int m0 = row0 + 2 * lane;
    if (m0 < M) {
        float2 p0 = unpack2(a00), p1 = unpack2(a01);
        __half2 h0 = __float22half2_rn(p0);
        __half2 h1 = __float22half2_rn(p1);
        uint2 pkt; pkt.x = *(uint32_t*)&h0; pkt.y = *(uint32_t*)&h1;
        *(uint2*)(g_t2 + (size_t)m0 * NC + c0) = pkt;
    }
    if (m0 + 1 < M) {
        float2 p0 = unpack2(a10), p1 = unpack2(a11);
        __half2 h0 = __float22half2_rn(p0);
        __half2 h1 = __float22half2_rn(p1);
        uint2 pkt; pkt.x = *(uint32_t*)&h0; pkt.y = *(uint32_t*)&h1;
        *(uint2*)(g_t2 + (size_t)(m0 + 1) * NC + c0) = pkt;
    }
}

// ---------------- agg2: out = A_norm @ t2 + b2  (t2 fp16, out fp32) ------
__global__ void k_agg2(const float* __restrict__ b2,
                       float* __restrict__ out,
                       int N) {
    int warp = threadIdx.x >> 5;
    int lane = threadIdx.x & 31;
    int n = blockIdx.x * (blockDim.x >> 5) + warp;
    if (n >= N) return;

    bool active = lane < 20;
    float di = g_dinv[n];
    float wself = di * di;

    float2 a = make_float2(0.f, 0.f);
    if (active) {
        __half2 v = ((const __half2*)(g_t2 + (size_t)n * NC))[lane];
        float2 f = __half22float2(v);
        a.x = f.x * wself;
        a.y = f.y * wself;
    }

    int e  = g_rowptr[n];
    int e1 = g_rowptr[n + 1];

    for (; e + 8 <= e1; e += 8) {
        int     si[8];
        float   wi[8];
        __half2 vi[8];
#pragma unroll
        for (int u = 0; u < 8; u++) si[u] = g_csr_src[e + u];
#pragma unroll
        for (int u = 0; u < 8; u++) wi[u] = g_csr_w[e + u] * di;
#pragma unroll
        for (int u = 0; u < 8; u++)
            vi[u] = active
                  ? ((const __half2*)(g_t2 + (size_t)si[u] * NC))[lane]
                  : __half2();
#pragma unroll
        for (int u = 0; u < 8; u++) {
            float2 f = __half22float2(vi[u]);
            a.x = fmaf(f.x, wi[u], a.x);
            a.y = fmaf(f.y, wi[u], a.y);
        }
    }
    for (; e < e1; e++) {
        int s   = g_csr_src[e];
        float w = g_csr_w[e] * di;
        if (active) {
            __half2 v = ((const __half2*)(g_t2 + (size_t)s * NC))[lane];
            float2 f = __half22float2(v);
            a.x = fmaf(f.x, w, a.x);
            a.y = fmaf(f.y, w, a.y);
        }
    }

    if (active) {
        float2 bv = ((const float2*)b2)[lane];
        float2 o = make_float2(a.x + bv.x, a.y + bv.y);
        *(float2*)(out + (size_t)n * NC + 2 * lane) = o;
    }
}

// ---------------- launch: fork gemm chain ∥ CSR chain ----------------
extern "C" void kernel_launch(void* const* d_in, const int* in_sizes, int n_in,
                              void* d_out, int out_size) {
    const float* x  = (const float*)d_in[0];
    const int*   ei = (const int*)d_in[1];
    const float* W1 = (const float*)d_in[2];
    const float* b1 = (const float*)d_in[3];
    const float* W2 = (const float*)d_in[4];
    const float* b2 = (const float*)d_in[5];
    float* out = (float*)d_out;

    const int N = N_NODES;
    const int E = N_EDGES;
    const int nb = (N + 1023) / 1024;   // 98

    // one-time host-side resources (created on first, uncaptured call)
    static cudaStream_t s_side = nullptr;
    static cudaEvent_t  ev_fork = nullptr, ev_join = nullptr;
    if (s_side == nullptr) {
        cudaStreamCreateWithFlags(&s_side, cudaStreamNonBlocking);
        cudaEventCreateWithFlags(&ev_fork, cudaEventDisableTiming);
        cudaEventCreateWithFlags(&ev_join, cudaEventDisableTiming);
    }

    // fork: gemm chain on side stream
    cudaEventRecord(ev_fork, 0);
    cudaStreamWaitEvent(s_side, ev_fork, 0);
    k_prep_wt <<<64, 256, 0, s_side>>>(W1);
    k_gemm1   <<<(N + 63) / 64, 256, 0, s_side>>>(x, N);
    cudaEventRecord(ev_join, s_side);

    // CSR chain on main stream (concurrent with gemm chain)
    k_zero  <<<(N + 255) / 256, 256>>>(N);
    k_count <<<(E + 255) / 256, 256>>>(ei, E);
    k_scan1 <<<nb, 1024>>>(N);
    k_scan3 <<<nb, 1024>>>(nb, N);
    k_fill  <<<(E + 255) / 256, 256>>>(ei, E);

    // join, then the dependent tail
    cudaStreamWaitEvent(0, ev_join, 0);
    k_agg1  <<<(N + 7) / 8, 256>>>(b1, N);
    k_gemm2 <<<(N + G2_ROWS - 1) / G2_ROWS, 320>>>(W2, N);
    k_agg2  <<<(N + 7) / 8, 256>>>(b2, out, N);
}

// round 15
// speedup vs baseline: 1.1129x; 1.0166x over previous
#include <cuda_runtime.h>
#include <cuda_fp16.h>
#include <stdint.h>

#define N_NODES 100000
#define N_EDGES 1600000
#define NF      128
#define NC      40

// ---------------- static scratch (no allocations allowed) ----------------
static __device__ __half g_h [(size_t)N_NODES * NF];        // 25.6 MB
static __device__ __half g_hd[(size_t)N_NODES * NF];        // 25.6 MB
static __device__ __half g_t2[(size_t)N_NODES * NC + 64];   // 8 MB (+pad)
static __device__ __half g_wt[128 * 128];                   // W1^T fp16
static __device__ float  g_dinv[N_NODES];
static __device__ int    g_cnt[N_NODES];
static __device__ int    g_rowptr[N_NODES + 1];
static __device__ int    g_cursor[N_NODES];
static __device__ int2   g_csr[N_EDGES];                    // (src, w-bits) 12.8 MB
static __device__ int    g_blocksum[128];

// ---------------- packed f32x2 helpers (Blackwell dual-rate fp32) --------
__device__ __forceinline__ uint64_t pack2(float lo, float hi) {
    uint64_t r;
    asm("mov.b64 %0, {%1, %2};" : "=l"(r) : "f"(lo), "f"(hi));
    return r;
}
__device__ __forceinline__ void fma2(uint64_t& d, uint64_t a, uint64_t b) {
    asm("fma.rn.f32x2 %0, %1, %2, %0;" : "+l"(d) : "l"(a), "l"(b));
}
__device__ __forceinline__ float2 unpack2(uint64_t v) {
    float2 f;
    asm("mov.b64 {%0, %1}, %2;" : "=f"(f.x), "=f"(f.y) : "l"(v));
    return f;
}

// ---------------- threefry2x32, key = (0, 42) ----------------
__device__ __forceinline__ uint32_t rotl32(uint32_t x, int r) {
    return (x << r) | (x >> (32 - r));
}

__device__ __forceinline__ void threefry_0_42(uint32_t& x0, uint32_t& x1) {
    const uint32_t K1 = 0u;
    const uint32_t K2 = 42u;
    const uint32_t KC = 0x1BD11BDAu ^ K1 ^ K2;
#define TF_ROUND(r) { x0 += x1; x1 = rotl32(x1, r); x1 ^= x0; }
    x0 += K1; x1 += K2;
    TF_ROUND(13) TF_ROUND(15) TF_ROUND(26) TF_ROUND(6)
    x0 += K2; x1 += KC + 1u;
    TF_ROUND(17) TF_ROUND(29) TF_ROUND(16) TF_ROUND(24)
    x0 += KC; x1 += K1 + 2u;
    TF_ROUND(13) TF_ROUND(15) TF_ROUND(26) TF_ROUND(6)
    x0 += K1; x1 += K2 + 3u;
    TF_ROUND(17) TF_ROUND(29) TF_ROUND(16) TF_ROUND(24)
    x0 += K2; x1 += KC + 4u;
    TF_ROUND(13) TF_ROUND(15) TF_ROUND(26) TF_ROUND(6)
    x0 += KC; x1 += K1 + 5u;
#undef TF_ROUND
}

__device__ __forceinline__ float drop_scale(uint32_t i) {
    uint32_t a = 0u, b = i;
    threefry_0_42(a, b);
    return ((a ^ b) >> 31) ? 2.0f : 0.0f;
}

// -------- prep: g_wt[n][k] = (half)W1[k][n] --------
__global__ void k_prep_wt(const float* __restrict__ W) {
    int idx = blockIdx.x * 256 + threadIdx.x;   // 64 blocks x 256
    int k = idx >> 7;
    int n = idx & 127;
    g_wt[n * 128 + k] = __float2half(W[(size_t)k * 128 + n]);
}

// ---------------- small kernels: degree / CSR build ----------------
__global__ void k_zero(int N) {
    int i = blockIdx.x * blockDim.x + threadIdx.x;
    if (i < N) g_cnt[i] = 0;
}

// 4 edges per thread (E divisible by 4)
__global__ void k_count(const int* __restrict__ ei, int E) {
    int q = blockIdx.x * blockDim.x + threadIdx.x;
    if (q < E / 4) {
        int4 d = *(const int4*)(ei + E + q * 4);
        atomicAdd(&g_cnt[d.x], 1);
        atomicAdd(&g_cnt[d.y], 1);
        atomicAdd(&g_cnt[d.z], 1);
        atomicAdd(&g_cnt[d.w], 1);
    }
}

__global__ void k_scan1(int N) {  // per-1024-block sums
    __shared__ int s[1024];
    int t = threadIdx.x;
    int i = blockIdx.x * 1024 + t;
    s[t] = (i < N) ? g_cnt[i] : 0;
    __syncthreads();
    for (int off = 512; off > 0; off >>= 1) {
        if (t < off) s[t] += s[t + off];
        __syncthreads();
    }
    if (t == 0) g_blocksum[blockIdx.x] = s[0];
}

// scan3 folds the cross-block exclusive scan: each block parallel-reduces
// g_blocksum[0..blockIdx.x) for its base.
__global__ void k_scan3(int nb, int N) {
    __shared__ int s[1024];
    __shared__ int aux[128];
    int t = threadIdx.x;
    int i = blockIdx.x * 1024 + t;
    if (t < 128) aux[t] = (t < blockIdx.x && t < nb) ? g_blocksum[t] : 0;
    int v = (i < N) ? g_cnt[i] : 0;
    s[t] = v;
    __syncthreads();
    if (t < 64) aux[t] += aux[t + 64];
    __syncthreads();
    if (t < 32) aux[t] += aux[t + 32];
    __syncthreads();
    if (t < 16) aux[t] += aux[t + 16];
    __syncthreads();
    if (t < 8)  aux[t] += aux[t + 8];
    __syncthreads();
    if (t < 4)  aux[t] += aux[t + 4];
    __syncthreads();
    if (t < 2)  aux[t] += aux[t + 2];
    __syncthreads();
    if (t < 1)  aux[t] += aux[t + 1];
    __syncthreads();
    int base = aux[0];
    for (int off = 1; off < 1024; off <<= 1) {
        int x = (t >= off) ? s[t - off] : 0;
        __syncthreads();
        s[t] += x;
        __syncthreads();
    }
    if (i < N) {
        int excl = s[t] - v + base;
        g_rowptr[i] = excl;
        g_cursor[i] = excl;
        g_dinv[i]   = rsqrtf((float)(v + 1));
        if (i == N - 1) g_rowptr[N] = excl + v;
    }
}

// fill writes packed (src, dinv[src]) pairs: one STG.64 per edge.
__global__ void k_fill(const int* __restrict__ ei, int E) {
    int e = blockIdx.x * blockDim.x + threadIdx.x;
    if (e < E) {
        int d   = ei[E + e];
        int s   = ei[e];
        int pos = atomicAdd(&g_cursor[d], 1);
        g_csr[pos] = make_int2(s, __float_as_int(g_dinv[s]));
    }
}

// ---------------- GEMM1: h = x @ W1, fp16 tensor cores (mma.sync) --------
__device__ __forceinline__ void mma16816(float c[4],
                                         uint32_t a0, uint32_t a1,
                                         uint32_t a2, uint32_t a3,
                                         uint32_t b0, uint32_t b1) {
    asm volatile(
        "mma.sync.aligned.m16n8k16.row.col.f32.f16.f16.f32 "
        "{%0,%1,%2,%3}, {%4,%5,%6,%7}, {%8,%9}, {%0,%1,%2,%3};"
        : "+f"(c[0]), "+f"(c[1]), "+f"(c[2]), "+f"(c[3])
        : "r"(a0), "r"(a1), "r"(a2), "r"(a3), "r"(b0), "r"(b1));
}

__device__ __forceinline__ uint32_t f2h2(float2 v) {
    __half2 h = __floats2half2_rn(v.x, v.y);
    return *(uint32_t*)&h;
}

__global__ __launch_bounds__(256, 3) void k_gemm1(const float* __restrict__ x,
                                                  int M) {
    __shared__ __align__(16) __half Wt[128 * 128];  // 32 KB, rotated rows

    int tid  = threadIdx.x;
    int row0 = blockIdx.x * 64;

    for (int i = tid; i < 128 * 16; i += 256) {
        int n = i >> 4;
        int s = i & 15;
        ((uint4*)(Wt + n * 128))[(s + (n & 15)) & 15] =
            ((const uint4*)(g_wt + n * 128))[s];
    }
    __syncthreads();

    int warp = tid >> 5;
    int lane = tid & 31;
    int g = lane >> 2;
    int t = lane & 3;
    int rg = warp >> 1;
    int ch = warp & 1;

    int r_lo = row0 + rg * 16 + g;
    int r_hi = r_lo + 8;
    bool lo_ok = r_lo < M;
    bool hi_ok = r_hi < M;
    const float* xlo = x + (size_t)r_lo * 128 + 2 * t;
    const float* xhi = x + (size_t)r_hi * 128 + 2 * t;

    float acc[8][4];
#pragma unroll
    for (int nt = 0; nt < 8; nt++)
#pragma unroll
        for (int j = 0; j < 4; j++) acc[nt][j] = 0.f;

#pragma unroll
    for (int k0 = 0; k0 < 128; k0 += 16) {
        uint32_t a0 = 0u, a1 = 0u, a2 = 0u, a3 = 0u;
        if (lo_ok) {
            a0 = f2h2(__ldcs((const float2*)(xlo + k0)));
            a2 = f2h2(__ldcs((const float2*)(xlo + k0 + 8)));
        }
        if (hi_ok) {
            a1 = f2h2(__ldcs((const float2*)(xhi + k0)));
            a3 = f2h2(__ldcs((const float2*)(xhi + k0 + 8)));
        }
#pragma unroll
        for (int nt = 0; nt < 8; nt++) {
            int n  = ch * 64 + nt * 8 + g;
            int rot = 8 * (n & 15);
            int h0 = (k0 + 2 * t + rot) & 127;
            int h1 = (k0 + 2 * t + 8 + rot) & 127;
            uint32_t b0 = *(uint32_t*)&Wt[n * 128 + h0];
            uint32_t b1 = *(uint32_t*)&Wt[n * 128 + h1];
            mma16816(acc[nt], a0, a1, a2, a3, b0, b1);
        }
    }

#pragma unroll
    for (int nt = 0; nt < 8; nt++) {
        int col = ch * 64 + nt * 8 + 2 * t;
        if (lo_ok) {
            __half2 hv = __floats2half2_rn(acc[nt][0], acc[nt][1]);
            *(uint32_t*)(g_h + (size_t)r_lo * 128 + col) = *(uint32_t*)&hv;
        }
        if (hi_ok) {
            __half2 hv = __floats2half2_rn(acc[nt][2], acc[nt][3]);
            *(uint32_t*)(g_h + (size_t)r_hi * 128 + col) = *(uint32_t*)&hv;
        }
    }
}

// ---- agg1: hd = dropout(relu(A_norm @ h + b1)), fp16, node range [n0,n1) -
__device__ __forceinline__ void acc_half4(float4& acc, uint2 raw, float w) {
    __half2 lo = *(__half2*)&raw.x;
    __half2 hi = *(__half2*)&raw.y;
    float2 f0 = __half22float2(lo);
    float2 f1 = __half22float2(hi);
    acc.x = fmaf(f0.x, w, acc.x);
    acc.y = fmaf(f0.y, w, acc.y);
    acc.z = fmaf(f1.x, w, acc.z);
    acc.w = fmaf(f1.y, w, acc.w);
}

__global__ void k_agg1(const float* __restrict__ b1, int n0, int n1) {
    int warp = threadIdx.x >> 5;
    int lane = threadIdx.x & 31;
    int n = n0 + blockIdx.x * (blockDim.x >> 5) + warp;
    if (n >= n1) return;

    float di = g_dinv[n];
    float wself = di * di;

    float4 acc = make_float4(0.f, 0.f, 0.f, 0.f);
    {
        uint2 raw = ((const uint2*)(g_h + (size_t)n * 128))[lane];
        acc_half4(acc, raw, wself);
    }

    int e  = g_rowptr[n];
    int e1 = g_rowptr[n + 1];

    for (; e + 8 <= e1; e += 8) {
        int2  p[8];
        float wi[8];
        uint2 vi[8];
#pragma unroll
        for (int u = 0; u < 8; u++) p[u] = g_csr[e + u];
#pragma unroll
        for (int u = 0; u < 8; u++) wi[u] = __int_as_float(p[u].y) * di;
#pragma unroll
        for (int u = 0; u < 8; u++)
            vi[u] = ((const uint2*)(g_h + (size_t)p[u].x * 128))[lane];
#pragma unroll
        for (int u = 0; u < 8; u++) acc_half4(acc, vi[u], wi[u]);
    }
    for (; e < e1; e++) {
        int2 p = g_csr[e];
        float w = __int_as_float(p.y) * di;
        uint2 raw = ((const uint2*)(g_h + (size_t)p.x * 128))[lane];
        acc_half4(acc, raw, w);
    }

    uint32_t mi = (uint32_t)n * 128u + (uint32_t)lane * 4u;
    float4 bb = ((const float4*)b1)[lane];
    float f0 = fmaxf(acc.x + bb.x, 0.f) * drop_scale(mi + 0u);
    float f1 = fmaxf(acc.y + bb.y, 0.f) * drop_scale(mi + 1u);
    float f2 = fmaxf(acc.z + bb.z, 0.f) * drop_scale(mi + 2u);
    float f3 = fmaxf(acc.w + bb.w, 0.f) * drop_scale(mi + 3u);

    __half2 h0 = __floats2half2_rn(f0, f1);
    __half2 h1 = __floats2half2_rn(f2, f3);
    uint2 pkt;
    pkt.x = *(uint32_t*)&h0;
    pkt.y = *(uint32_t*)&h1;
    ((uint2*)(g_hd + (size_t)n * 128))[lane] = pkt;
}

// ---------------- GEMM2: t2 = hd @ W2, rows [r0, M) chunk ----------------
#define G2_ROWS 64
__global__ __launch_bounds__(320) void k_gemm2(const float* __restrict__ W2,
                                               int r0, int M) {
    __shared__ __align__(16) __half Xs[128 * G2_ROWS];   // 16 KB
    __shared__ __align__(16) float  Ws[128 * NC];        // 20 KB

    int tid  = threadIdx.x;
    int row0 = r0 + blockIdx.x * G2_ROWS;

    for (int i = tid; i < 128 * NC / 4; i += 320)
        ((float4*)Ws)[i] = ((const float4*)W2)[i];

    for (int i = tid; i < G2_ROWS * 16; i += 320) {
        int m  = i / 16;
        int k8 = (i % 16) * 8;
        uint4 v = make_uint4(0u, 0u, 0u, 0u);
        if (row0 + m < M)
            v = ((const uint4*)(g_hd + (size_t)(row0 + m) * 128))[i % 16];
        __half* hp = (__half*)&v;
#pragma unroll
        for (int j = 0; j < 8; j++) Xs[(k8 + j) * G2_ROWS + m] = hp[j];
    }
    __syncthreads();

    int w    = tid >> 5;
    int lane = tid & 31;
    int c0   = w * 4;

    uint64_t a00 = pack2(0.f, 0.f), a01 = a00;
    uint64_t a10 = a00, a11 = a00;

#pragma unroll 4
    for (int k = 0; k < 128; k++) {
        __half2 xv = *(__half2*)&Xs[k * G2_ROWS + 2 * lane];
        float2  xf = __half22float2(xv);
        float4  wv = *(const float4*)&Ws[k * NC + c0];
        uint64_t w01 = pack2(wv.x, wv.y);
        uint64_t w23 = pack2(wv.z, wv.w);
        uint64_t x0  = pack2(xf.x, xf.x);
        uint64_t x1  = pack2(xf.y, xf.y);
        fma2(a00, x0, w01); fma2(a01, x0, w23);
        fma2(a10, x1, w01); fma2(a11, x1, w23);
    }

    int m0 = row0 + 2 * lane;
    if (m0 < M) {
        float2 p0 = unpack2(a00), p1 = unpack2(a01);
        __half2 h0 = __float22half2_rn(p0);
        __half2 h1 = __float22half2_rn(p1);
        uint2 pkt; pkt.x = *(uint32_t*)&h0; pkt.y = *(uint32_t*)&h1;
        *(uint2*)(g_t2 + (size_t)m0 * NC + c0) = pkt;
    }
    if (m0 + 1 < M) {
        float2 p0 = unpack2(a10), p1 = unpack2(a11);
        __half2 h0 = __float22half2_rn(p0);
        __half2 h1 = __float22half2_rn(p1);
        uint2 pkt; pkt.x = *(uint32_t*)&h0; pkt.y = *(uint32_t*)&h1;
        *(uint2*)(g_t2 + (size_t)(m0 + 1) * NC + c0) = pkt;
    }
}

// ---------------- agg2: out = A_norm @ t2 + b2  (t2 fp16, out fp32) ------
__global__ void k_agg2(const float* __restrict__ b2,
                       float* __restrict__ out,
                       int N) {
    int warp = threadIdx.x >> 5;
    int lane = threadIdx.x & 31;
    int n = blockIdx.x * (blockDim.x >> 5) + warp;
    if (n >= N) return;

    bool active = lane < 20;
    float di = g_dinv[n];
    float wself = di * di;

    float2 a = make_float2(0.f, 0.f);
    if (active) {
        __half2 v = ((const __half2*)(g_t2 + (size_t)n * NC))[lane];
        float2 f = __half22float2(v);
        a.x = f.x * wself;
        a.y = f.y * wself;
    }

    int e  = g_rowptr[n];
    int e1 = g_rowptr[n + 1];

    for (; e + 8 <= e1; e += 8) {
        int2    p[8];
        float   wi[8];
        __half2 vi[8];
#pragma unroll
        for (int u = 0; u < 8; u++) p[u] = g_csr[e + u];
#pragma unroll
        for (int u = 0; u < 8; u++) wi[u] = __int_as_float(p[u].y) * di;
#pragma unroll
        for (int u = 0; u < 8; u++)
            vi[u] = active
                  ? ((const __half2*)(g_t2 + (size_t)p[u].x * NC))[lane]
                  : __half2();
#pragma unroll
        for (int u = 0; u < 8; u++) {
            float2 f = __half22float2(vi[u]);
            a.x = fmaf(f.x, wi[u], a.x);
            a.y = fmaf(f.y, wi[u], a.y);
        }
    }
    for (; e < e1; e++) {
        int2 p = g_csr[e];
        float w = __int_as_float(p.y) * di;
        if (active) {
            __half2 v = ((const __half2*)(g_t2 + (size_t)p.x * NC))[lane];
            float2 f = __half22float2(v);
            a.x = fmaf(f.x, w, a.x);
            a.y = fmaf(f.y, w, a.y);
        }
    }

    if (active) {
        float2 bv = ((const float2*)b2)[lane];
        float2 o = make_float2(a.x + bv.x, a.y + bv.y);
        *(float2*)(out + (size_t)n * NC + 2 * lane) = o;
    }
}

// ------- launch: fork gemm chain ∥ CSR chain; pipeline agg1/gemm2 --------
extern "C" void kernel_launch(void* const* d_in, const int* in_sizes, int n_in,
                              void* d_out, int out_size) {
    const float* x  = (const float*)d_in[0];
    const int*   ei = (const int*)d_in[1];
    const float* W1 = (const float*)d_in[2];
    const float* b1 = (const float*)d_in[3];
    const float* W2 = (const float*)d_in[4];
    const float* b2 = (const float*)d_in[5];
    float* out = (float*)d_out;

    const int N = N_NODES;
    const int E = N_EDGES;
    const int nb = (N + 1023) / 1024;   // 98
    const int H0 = 50048;               // 782 * 64, chunk boundary

    // one-time host-side resources (created on first, uncaptured call)
    static cudaStream_t s_side = nullptr;
    static cudaEvent_t  evF = nullptr, evJ = nullptr, evA = nullptr,
                        evB = nullptr, evJ2 = nullptr;
    if (s_side == nullptr) {
        cudaStreamCreateWithFlags(&s_side, cudaStreamNonBlocking);
        cudaEventCreateWithFlags(&evF,  cudaEventDisableTiming);
        cudaEventCreateWithFlags(&evJ,  cudaEventDisableTiming);
        cudaEventCreateWithFlags(&evA,  cudaEventDisableTiming);
        cudaEventCreateWithFlags(&evB,  cudaEventDisableTiming);
        cudaEventCreateWithFlags(&evJ2, cudaEventDisableTiming);
    }

    // fork: gemm chain on side stream
    cudaEventRecord(evF, 0);
    cudaStreamWaitEvent(s_side, evF, 0);
    k_prep_wt <<<64, 256, 0, s_side>>>(W1);
    k_gemm1   <<<(N + 63) / 64, 256, 0, s_side>>>(x, N);
    cudaEventRecord(evJ, s_side);

    // CSR chain on main stream (concurrent with gemm chain)
    k_zero  <<<(N + 255) / 256, 256>>>(N);
    k_count <<<(E / 4 + 255) / 256, 256>>>(ei, E);
    k_scan1 <<<nb, 1024>>>(N);
    k_scan3 <<<nb, 1024>>>(nb, N);
    k_fill  <<<(E + 255) / 256, 256>>>(ei, E);

    // join gemm1, then pipelined agg1 / gemm2 chunks
    cudaStreamWaitEvent(0, evJ, 0);
    k_agg1 <<<(H0 + 7) / 8, 256>>>(b1, 0, H0);
    cudaEventRecord(evA, 0);
    k_agg1 <<<(N - H0 + 7) / 8, 256>>>(b1, H0, N);
    cudaEventRecord(evB, 0);

    cudaStreamWaitEvent(s_side, evA, 0);
    k_gemm2 <<<H0 / G2_ROWS, 320, 0, s_side>>>(W2, 0, H0);       // ∥ agg1 c1
    cudaStreamWaitEvent(s_side, evB, 0);
    k_gemm2 <<<(N - H0 + G2_ROWS - 1) / G2_ROWS, 320, 0, s_side>>>(W2, H0, N);
    cudaEventRecord(evJ2, s_side);

    cudaStreamWaitEvent(0, evJ2, 0);
    k_agg2 <<<(N + 7) / 8, 256>>>(b2, out, N);
}